// round 4
// baseline (speedup 1.0000x reference)
#include <cuda_runtime.h>
#include <math.h>

// Problem constants: N=100000, L=48, E=1600000, ED=17, H=48
#define NN 100000
#define LL 48
#define EE 1600000
#define EDD 17
#define CAP (1<<18)
#define NCAP (1<<16)

__device__ float g_x[NN*LL];
__device__ float g_v[NN*LL];
__device__ float g_agg[NN*LL];
__device__ float g_wbase[EE];
// flags as BYTE arrays stored in uint words (for atomicOr), 16B aligned for uint4 staging
#define NWORDS_MAX ((NN+3)/4 + 4)
__device__ __align__(16) unsigned int g_flag1w[NWORDS_MAX];
__device__ __align__(16) unsigned int g_flag2w[NWORDS_MAX];
__device__ int g_list1[CAP];
__device__ int g_list2[CAP];
__device__ int g_list3[CAP];
__device__ int g_nlist1[NCAP];
__device__ int g_nlist2[NCAP];
__device__ int g_cnt[4];    // edge-list counters (1..3)
__device__ int g_ncnt[4];   // node-list counters (1..2)

__device__ __forceinline__ float geluf(float x) {
    return 0.5f * x * (1.0f + erff(x * 0.70710678118654752f));
}
__device__ __forceinline__ float sigm(float x) {
    return 1.0f / (1.0f + expf(-x));
}

// mark byte-flag via word atomicOr; returns true if it was previously 0
__device__ __forceinline__ bool mark_flag(unsigned int* fw, int s) {
    unsigned int sh = (s & 3) * 8;
    unsigned int old = atomicOr(&fw[s >> 2], 1u << sh);
    return ((old >> sh) & 0xffu) == 0u;
}

// ---------------------------------------------------------------------------
// Init: clear flag words, seed node 0, reset counters
// ---------------------------------------------------------------------------
__global__ void k_init(int nwords) {
    int i = blockIdx.x * blockDim.x + threadIdx.x;
    if (i < nwords) {
        unsigned int seed = (i == 0) ? 1u : 0u;   // byte 0 of word 0 = node 0
        g_flag1w[i] = seed;
        g_flag2w[i] = seed;
    }
    if (i == 0) {
        g_cnt[1] = g_cnt[2] = g_cnt[3] = 0;
        g_nlist1[0] = 0; g_nlist2[0] = 0;
        g_ncnt[1] = 1; g_ncnt[2] = 1;
    }
}

// ---------------------------------------------------------------------------
// Scan level 3: dst==0 edges. No flag reads. 8 edges/thread/iter,
// one ballot per chunk, rare path does warp-aggregated appends.
// ---------------------------------------------------------------------------
__global__ void k_scan3(const int* __restrict__ src, const int* __restrict__ dst, int e) {
    int tid = blockIdx.x * blockDim.x + threadIdx.x;
    int lane = threadIdx.x & 31;
    long long stride = (long long)gridDim.x * blockDim.x * 8;

    for (long long base = (long long)tid * 8;; base += stride) {
        if (!__ballot_sync(0xffffffffu, base < e)) break;
        bool w = base < e;
        int d[8];
        #pragma unroll
        for (int t = 0; t < 8; t++) d[t] = -1;
        if (w) {
            if (base + 8 <= e) {
                int4 a = __ldg((const int4*)(dst + base));
                int4 b = __ldg((const int4*)(dst + base + 4));
                d[0]=a.x; d[1]=a.y; d[2]=a.z; d[3]=a.w;
                d[4]=b.x; d[5]=b.y; d[6]=b.z; d[7]=b.w;
            } else {
                #pragma unroll
                for (int t = 0; t < 8; t++) if (base + t < e) d[t] = dst[base + t];
            }
        }
        int mymask = 0;
        #pragma unroll
        for (int t = 0; t < 8; t++) if (d[t] == 0) mymask |= 1 << t;

        if (__ballot_sync(0xffffffffu, mymask != 0)) {
            #pragma unroll
            for (int t = 0; t < 8; t++) {
                bool pred = (mymask >> t) & 1;
                unsigned int m = __ballot_sync(0xffffffffu, pred);
                if (!m) continue;
                int leader = __ffs(m) - 1;
                int pos0 = 0;
                if (lane == leader) pos0 = atomicAdd(&g_cnt[3], __popc(m));
                pos0 = __shfl_sync(0xffffffffu, pos0, leader);
                if (pred) {
                    int p = pos0 + __popc(m & ((1u << lane) - 1));
                    int i = (int)(base + t);
                    if (p < CAP) g_list3[p] = i;
                    int s = src[i];
                    if (mark_flag(g_flag2w, s)) {
                        int q = atomicAdd(&g_ncnt[2], 1);
                        if (q < NCAP) g_nlist2[q] = s;
                    }
                    if (mark_flag(g_flag1w, s)) {
                        int q = atomicAdd(&g_ncnt[1], 1);
                        if (q < NCAP) g_nlist1[q] = s;
                    }
                }
            }
        }
    }
}

// ---------------------------------------------------------------------------
// Scan levels 2 and 1: stage flag bytes into smem, probe via LDS.
// level==2: probe flag2, append list2, mark flag1/nlist1
// level==1: probe flag1, append list1
// ---------------------------------------------------------------------------
__global__ void k_scan_smem(const int* __restrict__ src, const int* __restrict__ dst,
                            int e, int nwords, int level) {
    extern __shared__ unsigned int sflag[];
    {
        const uint4* gs = (const uint4*)((level == 2) ? g_flag2w : g_flag1w);
        uint4* sd = (uint4*)sflag;
        int nq = (nwords + 3) >> 2;
        for (int i = threadIdx.x; i < nq; i += blockDim.x) sd[i] = gs[i];
    }
    __syncthreads();
    const unsigned char* sb = (const unsigned char*)sflag;

    int tid = blockIdx.x * blockDim.x + threadIdx.x;
    int lane = threadIdx.x & 31;
    long long stride = (long long)gridDim.x * blockDim.x * 8;
    int* cnt  = (level == 2) ? &g_cnt[2] : &g_cnt[1];
    int* list = (level == 2) ? g_list2 : g_list1;

    for (long long base = (long long)tid * 8;; base += stride) {
        if (!__ballot_sync(0xffffffffu, base < e)) break;
        bool w = base < e;
        int d[8];
        #pragma unroll
        for (int t = 0; t < 8; t++) d[t] = -1;
        if (w) {
            if (base + 8 <= e) {
                int4 a = __ldg((const int4*)(dst + base));
                int4 b = __ldg((const int4*)(dst + base + 4));
                d[0]=a.x; d[1]=a.y; d[2]=a.z; d[3]=a.w;
                d[4]=b.x; d[5]=b.y; d[6]=b.z; d[7]=b.w;
            } else {
                #pragma unroll
                for (int t = 0; t < 8; t++) if (base + t < e) d[t] = dst[base + t];
            }
        }
        int mymask = 0;
        #pragma unroll
        for (int t = 0; t < 8; t++) if (d[t] >= 0 && sb[d[t]]) mymask |= 1 << t;

        if (__ballot_sync(0xffffffffu, mymask != 0)) {
            #pragma unroll
            for (int t = 0; t < 8; t++) {
                bool pred = (mymask >> t) & 1;
                unsigned int m = __ballot_sync(0xffffffffu, pred);
                if (!m) continue;
                int leader = __ffs(m) - 1;
                int pos0 = 0;
                if (lane == leader) pos0 = atomicAdd(cnt, __popc(m));
                pos0 = __shfl_sync(0xffffffffu, pos0, leader);
                if (pred) {
                    int p = pos0 + __popc(m & ((1u << lane) - 1));
                    int i = (int)(base + t);
                    if (p < CAP) list[p] = i;
                    if (level == 2) {
                        int s = src[i];
                        if (mark_flag(g_flag1w, s)) {
                            int q = atomicAdd(&g_ncnt[1], 1);
                            if (q < NCAP) g_nlist1[q] = s;
                        }
                    }
                }
            }
        }
    }
}

// ---------------------------------------------------------------------------
// wbase for list1 edges + zero g_agg for nlist1 nodes (independent loops)
// ---------------------------------------------------------------------------
__global__ void k_wbase_zero(const float* __restrict__ ea_all,
                             const float* __restrict__ W1, const float* __restrict__ b1,
                             const float* __restrict__ W2, const float* __restrict__ b2,
                             const float* __restrict__ Wg, const float* __restrict__ bg,
                             const float* __restrict__ Ww, const float* __restrict__ bw) {
    // zero phase
    {
        int total = min(g_ncnt[1], NCAP) * LL;
        for (int q = blockIdx.x * blockDim.x + threadIdx.x; q < total;
             q += gridDim.x * blockDim.x) {
            int u = g_nlist1[q / LL];
            g_agg[(long long)u * LL + (q % LL)] = 0.f;
        }
    }
    // wbase phase
    int lane  = threadIdx.x & 31;
    int warp  = (blockIdx.x * blockDim.x + threadIdx.x) >> 5;
    int nwarp = (gridDim.x * blockDim.x) >> 5;
    int cnt = min(g_cnt[1], CAP);
    bool lo = (lane < 16);

    for (int it = warp; it < cnt; it += nwarp) {
        int e = g_list1[it];
        const float* ea = ea_all + (long long)e * EDD;

        float a  = b1[lane];
        float a2 = lo ? b1[lane + 32] : 0.f;
        #pragma unroll
        for (int k = 0; k < EDD; k++) {
            float ev = __ldg(&ea[k]);
            a = fmaf(ev, W1[k * 48 + lane], a);
            if (lo) a2 = fmaf(ev, W1[k * 48 + lane + 32], a2);
        }
        a = geluf(a); a2 = geluf(a2);

        float c  = b2[lane];
        float c2 = lo ? b2[lane + 32] : 0.f;
        #pragma unroll
        for (int k = 0; k < 48; k++) {
            float hk = (k < 32) ? __shfl_sync(0xffffffffu, a, k)
                                : __shfl_sync(0xffffffffu, a2, k - 32);
            c = fmaf(hk, W2[k * 48 + lane], c);
            if (lo) c2 = fmaf(hk, W2[k * 48 + lane + 32], c2);
        }
        c = fmaxf(c, 0.f); c2 = fmaxf(c2, 0.f);

        float d1 = bg[lane];
        float d2 = lo ? bg[lane + 32] : 0.f;
        #pragma unroll
        for (int k = 0; k < 48; k++) {
            float hk = (k < 32) ? __shfl_sync(0xffffffffu, c, k)
                                : __shfl_sync(0xffffffffu, c2, k - 32);
            d1 = fmaf(hk, Wg[k * 48 + lane], d1);
            if (lo) d2 = fmaf(hk, Wg[k * 48 + lane + 32], d2);
        }
        d1 = geluf(d1); d2 = geluf(d2);

        float p = d1 * Ww[lane] + (lo ? d2 * Ww[lane + 32] : 0.f);
        #pragma unroll
        for (int off = 16; off; off >>= 1) p += __shfl_xor_sync(0xffffffffu, p, off);
        if (lane == 0) g_wbase[e] = p + bw[0];
    }
}

// ---------------------------------------------------------------------------
// Level-1 aggregate (reads x0/v0 from nodes*valid on the fly)
// ---------------------------------------------------------------------------
__global__ void k_agg1(const int* __restrict__ src, const int* __restrict__ dst,
                       const float* __restrict__ nodes, const float* __restrict__ valid) {
    int lane  = threadIdx.x & 31;
    int warp  = (blockIdx.x * blockDim.x + threadIdx.x) >> 5;
    int nwarp = (gridDim.x * blockDim.x) >> 5;
    int cnt = min(g_cnt[1], CAP);
    bool lo = (lane < 16);

    for (int it = warp; it < cnt; it += nwarp) {
        int e = g_list1[it];
        int s = __ldg(&src[e]);
        int d = __ldg(&dst[e]);
        long long sb = (long long)s * LL;

        float v0 = __ldg(&valid[sb + lane]);
        float v1 = lo ? __ldg(&valid[sb + lane + 32]) : 0.f;
        float x0 = __ldg(&nodes[sb + lane]) * v0;
        float x1 = lo ? __ldg(&nodes[sb + lane + 32]) * v1 : 0.f;

        float sv = v0 + v1;
        #pragma unroll
        for (int off = 16; off; off >>= 1) sv += __shfl_xor_sync(0xffffffffu, sv, off);
        float sg = sigm((sv * (1.0f / 48.0f)) * g_wbase[e]);

        float* ad = g_agg + (long long)d * LL;
        atomicAdd(&ad[lane], x0 * sg);
        if (lo) atomicAdd(&ad[lane + 32], x1 * sg);
    }
}

// ---------------------------------------------------------------------------
// Level-1 node update over nlist1 (also re-zeroes agg for level 2)
// ---------------------------------------------------------------------------
__global__ void k_upd1(const float* __restrict__ nodes, const float* __restrict__ valid,
                       const float* __restrict__ Wf, const float* __restrict__ bf) {
    int cnt = min(g_ncnt[1], NCAP);
    int total = cnt * LL;
    float wf0 = Wf[0], wf1 = Wf[1], wf2 = Wf[2], b0 = bf[0];

    for (int q = blockIdx.x * blockDim.x + threadIdx.x; q < total;
         q += gridDim.x * blockDim.x) {
        int u = g_nlist1[q / LL];
        int l = q % LL;
        long long i = (long long)u * LL + l;

        float vo = __ldg(&valid[i]);
        float orig = __ldg(&nodes[i]) * vo;
        float xo = orig;

        float nh = g_agg[i];
        float nv = 1.0f - vo;
        float m  = sigm(nh * wf0 + xo * wf1 + nv * wf2 + b0);
        float xn = (1.0f - m) * xo + nv * m * nh;
        float vn = (l != 0 && (orig != xn || vo > 0.0f)) ? 1.0f : 0.0f;
        g_x[i] = xn;
        g_v[i] = vn;
        g_agg[i] = 0.f;
    }
}

// ---------------------------------------------------------------------------
// Fused level-2: agg over list2 (from g_x/g_v) + update over nlist2.
// Single block: __syncthreads orders agg atomics before update reads.
// ---------------------------------------------------------------------------
__global__ void k_lvl2(const float* __restrict__ nodes, const float* __restrict__ valid,
                       const float* __restrict__ Wf, const float* __restrict__ bf) {
    int lane = threadIdx.x & 31;
    int warp = threadIdx.x >> 5;
    int nwarp = blockDim.x >> 5;
    bool lo = (lane < 16);
    int cnt = min(g_cnt[2], CAP);

    for (int it = warp; it < cnt; it += nwarp) {
        int e = g_list2[it];
        // src/dst fetched from wbase-independent arrays via pointers passed through lists
        // (src/dst pointers unavailable here; see k_lvl2 launch: they are passed)
        // -- replaced below in real signature --
        (void)e;
    }
    (void)nodes; (void)valid; (void)Wf; (void)bf; (void)lo;
}

// real fused level kernel (level = 2 or 3)
__global__ void k_lvl_fused(const int* __restrict__ src, const int* __restrict__ dst,
                            const float* __restrict__ nodes, const float* __restrict__ valid,
                            const float* __restrict__ Wf, const float* __restrict__ bf,
                            int level, float* __restrict__ out) {
    int lane = threadIdx.x & 31;
    int warp = threadIdx.x >> 5;
    int nwarp = blockDim.x >> 5;
    bool lo = (lane < 16);
    const int* list = (level == 2) ? g_list2 : g_list3;
    int cnt = min(g_cnt[level], CAP);

    for (int it = warp; it < cnt; it += nwarp) {
        int e = list[it];
        int s = __ldg(&src[e]);
        int d = __ldg(&dst[e]);
        long long sb = (long long)s * LL;

        float v0 = g_v[sb + lane];
        float v1 = lo ? g_v[sb + lane + 32] : 0.f;
        float x0 = g_x[sb + lane];
        float x1 = lo ? g_x[sb + lane + 32] : 0.f;

        float sv = v0 + v1;
        #pragma unroll
        for (int off = 16; off; off >>= 1) sv += __shfl_xor_sync(0xffffffffu, sv, off);
        float sg = sigm((sv * (1.0f / 48.0f)) * g_wbase[e]);

        float* ad = g_agg + (long long)d * LL;
        atomicAdd(&ad[lane], x0 * sg);
        if (lo) atomicAdd(&ad[lane + 32], x1 * sg);
    }

    __syncthreads();   // agg atomics visible block-wide

    int ncnt = (level == 2) ? min(g_ncnt[2], NCAP) : 1;
    int total = ncnt * LL;
    float wf0 = Wf[0], wf1 = Wf[1], wf2 = Wf[2], b0 = bf[0];

    for (int q = threadIdx.x; q < total; q += blockDim.x) {
        int u = (level == 2) ? g_nlist2[q / LL] : 0;
        int l = q % LL;
        long long i = (long long)u * LL + l;

        float vo2 = __ldg(&valid[i]);
        float orig = __ldg(&nodes[i]) * vo2;
        float xo = g_x[i];
        float vo = g_v[i];

        float nh = g_agg[i];
        float nv = 1.0f - vo;
        float m  = sigm(nh * wf0 + xo * wf1 + nv * wf2 + b0);
        float xn = (1.0f - m) * xo + nv * m * nh;
        float vn = (l != 0 && (orig != xn || vo > 0.0f)) ? 1.0f : 0.0f;
        g_x[i] = xn;
        g_v[i] = vn;
        g_agg[i] = 0.f;
        if (level == 3 && u == 0) out[l] = xn;
    }
}

extern "C" void kernel_launch(void* const* d_in, const int* in_sizes, int n_in,
                              void* d_out, int out_size) {
    const float* nodes     = (const float*)d_in[0];
    const int*   ei        = (const int*)d_in[1];
    const float* edge_attr = (const float*)d_in[2];
    const float* valid     = (const float*)d_in[3];
    const float* W1 = (const float*)d_in[6];
    const float* b1 = (const float*)d_in[7];
    const float* W2 = (const float*)d_in[8];
    const float* b2 = (const float*)d_in[9];
    const float* Wg = (const float*)d_in[10];
    const float* bg = (const float*)d_in[11];
    const float* Ww = (const float*)d_in[12];
    const float* bw = (const float*)d_in[13];
    const float* Wf = (const float*)d_in[14];
    const float* bf = (const float*)d_in[15];

    int n = in_sizes[0] / LL;
    int e = in_sizes[1] / 2;
    const int* src = ei;
    const int* dst = ei + e;
    int nwords = (n + 3) / 4;
    size_t smem = (size_t)(((nwords + 3) >> 2) << 2) * 4;   // padded to uint4

    static int attr_done = 0;
    if (!attr_done) {
        cudaFuncSetAttribute(k_scan_smem, cudaFuncAttributeMaxDynamicSharedMemorySize,
                             (int)smem);
        attr_done = 1;
    }

    k_init<<<(nwords + 255) / 256, 256>>>(nwords);
    k_scan3<<<296, 256>>>(src, dst, e);
    k_scan_smem<<<148, 512, smem>>>(src, dst, e, nwords, 2);
    k_scan_smem<<<148, 512, smem>>>(src, dst, e, nwords, 1);
    k_wbase_zero<<<148, 256>>>(edge_attr, W1, b1, W2, b2, Wg, bg, Ww, bw);
    k_agg1<<<148, 256>>>(src, dst, nodes, valid);
    k_upd1<<<64, 256>>>(nodes, valid, Wf, bf);
    k_lvl_fused<<<1, 1024>>>(src, dst, nodes, valid, Wf, bf, 2, (float*)d_out);
    k_lvl_fused<<<1, 256>>>(src, dst, nodes, valid, Wf, bf, 3, (float*)d_out);
}